// round 7
// baseline (speedup 1.0000x reference)
#include <cuda_runtime.h>
#include <cstdint>

// EmbeddingLSQ: out[t, d] = (idx[t]==0) ? 0 : round(clamp(W[d, idx[t]]/a, -8, 7))*a
// where idx[t] = argmax_v x[t, v]  (x is one-hot float32).
//
// Pipeline (3 kernels):
//  K1 find_idx : early-exit scan -> g_idx[], fused bucket histogram (atomicAdd g_cnt)
//  K2 sort     : ONE block: scan 2000 bucket counts + smem-atomic scatter into
//                g_order/g_sidx; re-zeroes g_cnt for the next call.
//  K3 gather   : warp-coalesced gather of W columns over sorted tokens,
//                smem transpose, coalesced output writes.
//
// Cross-call state: g_cnt is zero at entry (zero-init on first call, re-zeroed
// by K2 every call) -> every graph replay does identical work.

#define VOCAB    32000
#define DIM      1024
#define TOKENS   4096
#define NTHREADS 256
#define U4_PER_ROW (VOCAB / 4)          // 8000 uint4 per row
#define NBUCKETS (VOCAB / 16)           // 2000, each spans 64B of a W row
#define GROUP    32                     // tokens per gather group

__device__ int g_idx[TOKENS];
__device__ int g_cnt[NBUCKETS];         // zero at entry of every call
__device__ int g_order[TOKENS];
__device__ int g_sidx[TOKENS];

// ---------------- K1: find hot index (early exit) + fused histogram ----------------
__global__ __launch_bounds__(NTHREADS, 8)
void find_idx_kernel(const float* __restrict__ x) {
    const int t = blockIdx.x;
    __shared__ int s_idx;
    __shared__ int s_found;
    if (threadIdx.x == 0) { s_found = 0; s_idx = 0; }
    __syncthreads();

    const uint4* __restrict__ row =
        reinterpret_cast<const uint4*>(x + (size_t)t * VOCAB);
    volatile int* vflag = &s_found;

    for (int base = 0; base < 32; base++) {
        if (*vflag) break;
        const int j = threadIdx.x + base * NTHREADS;
        if (j < U4_PER_ROW) {
            uint4 v = row[j];
            if (v.x | v.y | v.z | v.w) {
                const int loc = v.x ? 0 : (v.y ? 1 : (v.z ? 2 : 3));
                s_idx = j * 4 + loc;       // unique writer (one-hot row)
                __threadfence_block();
                *vflag = 1;
            }
        }
    }
    __syncthreads();   // rendezvous: finder's s_idx visible to thread 0
    if (threadIdx.x == 0) {
        const int idx = s_idx;
        g_idx[t] = idx;
        atomicAdd(&g_cnt[idx >> 4], 1);    // fused histogram
    }
}

// ---------------- K2: one-block counting sort (scan + scatter) ----------------
__global__ __launch_bounds__(1024)
void sort_kernel() {
    __shared__ int bufA[2048], bufB[2048];
    const int tid = threadIdx.x;

    // load counts, and re-zero the global histogram for the next call
    for (int i = tid; i < 2048; i += 1024) {
        int c = 0;
        if (i < NBUCKETS) { c = g_cnt[i]; g_cnt[i] = 0; }
        bufA[i] = c;
    }
    __syncthreads();

    // inclusive Hillis-Steele scan over 2048
    int* src = bufA; int* dst = bufB;
    for (int d = 1; d < 2048; d <<= 1) {
        for (int i = tid; i < 2048; i += 1024)
            dst[i] = (i >= d) ? (src[i] + src[i - d]) : src[i];
        __syncthreads();
        int* tmp = src; src = dst; dst = tmp;
    }
    // exclusive offsets into dst (the free buffer)
    for (int i = tid; i < 2048; i += 1024)
        dst[i] = (i == 0) ? 0 : src[i - 1];
    __syncthreads();

    // scatter 4096 tokens via smem atomics (low contention: ~2 per bucket)
    #pragma unroll
    for (int k = 0; k < TOKENS / 1024; k++) {
        const int t = tid + k * 1024;
        const int idx = g_idx[t];
        const int pos = atomicAdd(&dst[idx >> 4], 1);
        g_order[pos] = t;
        g_sidx[pos]  = idx;
    }
}

// ---------------- K3: warp-coalesced gather + LSQ + transpose write ----------------
// grid = (TOKENS/GROUP, DIM/128); block = 256 (8 warps).
__global__ __launch_bounds__(NTHREADS)
void gather_lsq_kernel(const float* __restrict__ w,
                       const float* __restrict__ alpha,
                       float* __restrict__ out) {
    __shared__ int   s_tok[GROUP];
    __shared__ int   s_ix[GROUP];
    __shared__ float tile[32][33];

    const int tid  = threadIdx.x;
    const int warp = tid >> 5;
    const int lane = tid & 31;
    const int gbase  = blockIdx.x * GROUP;
    const int dbase0 = blockIdx.y * 128;

    if (tid < GROUP) {
        s_tok[tid] = g_order[gbase + tid];
        s_ix[tid]  = g_sidx[gbase + tid];
    }
    __syncthreads();

    const float a = __ldg(alpha);
    const int   myidx = s_ix[lane];        // lane <-> sorted token (load phase)
    const bool  pad   = (myidx == 0);

    #pragma unroll
    for (int c = 0; c < 4; c++) {
        const int dbase = dbase0 + c * 32;
        float wv[4];
        #pragma unroll
        for (int r = 0; r < 4; r++)
            wv[r] = __ldg(w + (size_t)(dbase + warp * 4 + r) * VOCAB + myidx);
        #pragma unroll
        for (int r = 0; r < 4; r++) {
            float q = pad ? 0.0f
                          : rintf(fminf(fmaxf(wv[r] / a, -8.0f), 7.0f)) * a;
            tile[warp * 4 + r][lane] = q;
        }
        __syncthreads();
        #pragma unroll
        for (int r = 0; r < 4; r++) {
            const int tl = warp * 4 + r;
            const int t  = s_tok[tl];
            out[(size_t)t * DIM + dbase + lane] = tile[lane][tl];
        }
        __syncthreads();
    }
}

extern "C" void kernel_launch(void* const* d_in, const int* in_sizes, int n_in,
                              void* d_out, int out_size) {
    const float* x     = (const float*)d_in[0];
    const float* w     = (const float*)d_in[1];
    const float* alpha = (const float*)d_in[2];
    float* out = (float*)d_out;

    find_idx_kernel<<<TOKENS, NTHREADS>>>(x);
    sort_kernel<<<1, 1024>>>();
    dim3 grid(TOKENS / GROUP, DIM / 128);
    gather_lsq_kernel<<<grid, NTHREADS>>>(w, alpha, out);
}

// round 8
// speedup vs baseline: 1.0515x; 1.0515x over previous
#include <cuda_runtime.h>
#include <cstdint>

// EmbeddingLSQ: out[t, d] = (idx[t]==0) ? 0 : round(clamp(W[d, idx[t]]/a, -8, 7))*a
// where idx[t] = argmax_v x[t, v]  (x is one-hot float32).
//
// Pipeline (3 kernels):
//  K1 find_idx : early-exit scan (batch-2 loads per flag poll -> MLP=2)
//                -> g_idx[], fused bucket histogram (atomicAdd g_cnt)
//  K2 sort     : ONE block: scan 2000 bucket counts + smem-atomic scatter into
//                g_order/g_sidx; re-zeroes g_cnt for the next call.
//  K3 gather   : warp-coalesced gather of W columns over sorted tokens,
//                smem transpose, coalesced output writes.
//
// Cross-call state: g_cnt is zero at entry (zero-init on first call, re-zeroed
// by K2 every call) -> every graph replay does identical work.

#define VOCAB    32000
#define DIM      1024
#define TOKENS   4096
#define NTHREADS 256
#define U4_PER_ROW (VOCAB / 4)          // 8000 uint4 per row
#define NBUCKETS (VOCAB / 16)           // 2000, each spans 64B of a W row
#define GROUP    32                     // tokens per gather group

__device__ int g_idx[TOKENS];
__device__ int g_cnt[NBUCKETS];         // zero at entry of every call
__device__ int g_order[TOKENS];
__device__ int g_sidx[TOKENS];

// ---------------- K1: find hot index (early exit, batch-2) + fused histogram ----------------
__global__ __launch_bounds__(NTHREADS, 8)
void find_idx_kernel(const float* __restrict__ x) {
    const int t = blockIdx.x;
    __shared__ int s_idx;
    __shared__ int s_found;
    if (threadIdx.x == 0) { s_found = 0; s_idx = 0; }
    __syncthreads();

    const uint4* __restrict__ row =
        reinterpret_cast<const uint4*>(x + (size_t)t * VOCAB);
    volatile int* vflag = &s_found;

    // Batch of 2 independent LDG.128 per flag poll: keeps MLP=2 per thread
    // (R7 showed poll-per-load serializes the loads and costs ~10% bandwidth).
    for (int base = 0; base < 32; base += 2) {
        if (*vflag) break;
        const int j0 = threadIdx.x + base * NTHREADS;
        const int j1 = j0 + NTHREADS;
        const bool p0 = (j0 < U4_PER_ROW);
        const bool p1 = (j1 < U4_PER_ROW);
        uint4 v0, v1;
        if (p0) v0 = row[j0];
        if (p1) v1 = row[j1];
        if (p0 && (v0.x | v0.y | v0.z | v0.w)) {
            const int loc = v0.x ? 0 : (v0.y ? 1 : (v0.z ? 2 : 3));
            s_idx = j0 * 4 + loc;          // unique writer (one-hot row)
            __threadfence_block();
            *vflag = 1;
        }
        if (p1 && (v1.x | v1.y | v1.z | v1.w)) {
            const int loc = v1.x ? 0 : (v1.y ? 1 : (v1.z ? 2 : 3));
            s_idx = j1 * 4 + loc;
            __threadfence_block();
            *vflag = 1;
        }
    }
    __syncthreads();   // rendezvous: finder's s_idx visible to thread 0
    if (threadIdx.x == 0) {
        const int idx = s_idx;
        g_idx[t] = idx;
        atomicAdd(&g_cnt[idx >> 4], 1);    // fused histogram
    }
}

// ---------------- K2: one-block counting sort (scan + scatter) ----------------
__global__ __launch_bounds__(1024)
void sort_kernel() {
    __shared__ int bufA[2048], bufB[2048];
    const int tid = threadIdx.x;

    // load counts, and re-zero the global histogram for the next call
    for (int i = tid; i < 2048; i += 1024) {
        int c = 0;
        if (i < NBUCKETS) { c = g_cnt[i]; g_cnt[i] = 0; }
        bufA[i] = c;
    }
    __syncthreads();

    // inclusive Hillis-Steele scan over 2048
    int* src = bufA; int* dst = bufB;
    for (int d = 1; d < 2048; d <<= 1) {
        for (int i = tid; i < 2048; i += 1024)
            dst[i] = (i >= d) ? (src[i] + src[i - d]) : src[i];
        __syncthreads();
        int* tmp = src; src = dst; dst = tmp;
    }
    // exclusive offsets into dst (the free buffer)
    for (int i = tid; i < 2048; i += 1024)
        dst[i] = (i == 0) ? 0 : src[i - 1];
    __syncthreads();

    // scatter 4096 tokens via smem atomics (low contention: ~2 per bucket)
    #pragma unroll
    for (int k = 0; k < TOKENS / 1024; k++) {
        const int t = tid + k * 1024;
        const int idx = g_idx[t];
        const int pos = atomicAdd(&dst[idx >> 4], 1);
        g_order[pos] = t;
        g_sidx[pos]  = idx;
    }
}

// ---------------- K3: warp-coalesced gather + LSQ + transpose write ----------------
// grid = (TOKENS/GROUP, DIM/128); block = 256 (8 warps).
__global__ __launch_bounds__(NTHREADS)
void gather_lsq_kernel(const float* __restrict__ w,
                       const float* __restrict__ alpha,
                       float* __restrict__ out) {
    __shared__ int   s_tok[GROUP];
    __shared__ int   s_ix[GROUP];
    __shared__ float tile[32][33];

    const int tid  = threadIdx.x;
    const int warp = tid >> 5;
    const int lane = tid & 31;
    const int gbase  = blockIdx.x * GROUP;
    const int dbase0 = blockIdx.y * 128;

    if (tid < GROUP) {
        s_tok[tid] = g_order[gbase + tid];
        s_ix[tid]  = g_sidx[gbase + tid];
    }
    __syncthreads();

    const float a = __ldg(alpha);
    const int   myidx = s_ix[lane];        // lane <-> sorted token (load phase)
    const bool  pad   = (myidx == 0);

    #pragma unroll
    for (int c = 0; c < 4; c++) {
        const int dbase = dbase0 + c * 32;
        float wv[4];
        #pragma unroll
        for (int r = 0; r < 4; r++)
            wv[r] = __ldg(w + (size_t)(dbase + warp * 4 + r) * VOCAB + myidx);
        #pragma unroll
        for (int r = 0; r < 4; r++) {
            float q = pad ? 0.0f
                          : rintf(fminf(fmaxf(wv[r] / a, -8.0f), 7.0f)) * a;
            tile[warp * 4 + r][lane] = q;
        }
        __syncthreads();
        #pragma unroll
        for (int r = 0; r < 4; r++) {
            const int tl = warp * 4 + r;
            const int t  = s_tok[tl];
            out[(size_t)t * DIM + dbase + lane] = tile[lane][tl];
        }
        __syncthreads();
    }
}

extern "C" void kernel_launch(void* const* d_in, const int* in_sizes, int n_in,
                              void* d_out, int out_size) {
    const float* x     = (const float*)d_in[0];
    const float* w     = (const float*)d_in[1];
    const float* alpha = (const float*)d_in[2];
    float* out = (float*)d_out;

    find_idx_kernel<<<TOKENS, NTHREADS>>>(x);
    sort_kernel<<<1, 1024>>>();
    dim3 grid(TOKENS / GROUP, DIM / 128);
    gather_lsq_kernel<<<grid, NTHREADS>>>(w, alpha, out);
}